// round 15
// baseline (speedup 1.0000x reference)
#include <cuda_runtime.h>

// Problem dims (fixed)
#define B_   2
#define S_   2048
#define D_   1024
#define H_   16
#define KS_  64
#define NKH_ (KS_ * H_)   // 1024
#define NBH_ (B_ * H_)    // 32

// Device scratch (allocation-free rule: device globals)
__device__ float g_q[NBH_ * S_ * KS_];      // [b,h,s,k]
__device__ float g_k[NBH_ * S_ * KS_];
__device__ float g_v[NBH_ * S_ * KS_];

// ---------------------------------------------------------------------------
// TF32 helpers
// ---------------------------------------------------------------------------
__device__ __forceinline__ unsigned f2tf32(float f) {
    unsigned r;
    asm("cvt.rna.tf32.f32 %0, %1;" : "=r"(r) : "f"(f));
    return r;
}
__device__ __forceinline__ float tf32f(float f) {
    return __uint_as_float(f2tf32(f));
}
__device__ __forceinline__ void mma_tf32(float* c, const unsigned* a, const unsigned* b) {
    asm volatile(
        "mma.sync.aligned.m16n8k8.row.col.f32.tf32.tf32.f32 "
        "{%0,%1,%2,%3}, {%4,%5,%6,%7}, {%8,%9}, {%0,%1,%2,%3};"
        : "+f"(c[0]), "+f"(c[1]), "+f"(c[2]), "+f"(c[3])
        : "r"(a[0]), "r"(a[1]), "r"(a[2]), "r"(a[3]), "r"(b[0]), "r"(b[1]));
}

// ---------------------------------------------------------------------------
// BF16 helpers: 3-term split (hi*hi + hi*lo + lo*hi)
// ---------------------------------------------------------------------------
__device__ __forceinline__ unsigned bf16pack(float lo, float hi) {
    unsigned r;
    asm("cvt.rn.bf16x2.f32 %0, %1, %2;" : "=r"(r) : "f"(hi), "f"(lo));
    return r;
}
__device__ __forceinline__ float bf16lo_f(unsigned p) { return __uint_as_float(p << 16); }
__device__ __forceinline__ float bf16hi_f(unsigned p) { return __uint_as_float(p & 0xffff0000u); }
__device__ __forceinline__ uint2 splitpair(float e0, float e1) {
    unsigned h = bf16pack(e0, e1);
    float r0 = e0 - bf16lo_f(h);
    float r1 = e1 - bf16hi_f(h);
    unsigned l = bf16pack(r0, r1);
    return make_uint2(h, l);
}
__device__ __forceinline__ void mma_bf16(float* c, const unsigned* a, const unsigned* b) {
    asm volatile(
        "mma.sync.aligned.m16n8k16.row.col.f32.bf16.bf16.f32 "
        "{%0,%1,%2,%3}, {%4,%5,%6,%7}, {%8,%9}, {%0,%1,%2,%3};"
        : "+f"(c[0]), "+f"(c[1]), "+f"(c[2]), "+f"(c[3])
        : "r"(a[0]), "r"(a[1]), "r"(a[2]), "r"(a[3]), "r"(b[0]), "r"(b[1]));
}

// ---------------------------------------------------------------------------
// Kernel 1: QKV projection GEMM, 3x-split bf16 m16n8k16, split-at-staging.
// MMA issue order is TERM-MAJOR: 16 independent accumulators between
// successive writes to the same acc tile (breaks HMMA RAW chains).
// ---------------------------------------------------------------------------
__global__ __launch_bounds__(256, 2) void qkv_gemm(
    const float* __restrict__ x,
    const float* __restrict__ Wq,
    const float* __restrict__ Wk,
    const float* __restrict__ Wv)
{
    __shared__ uint2 As2[2][8][132];   // 16.9 KB
    __shared__ uint2 Bs2[2][8][132];   // 16.9 KB

    const int bz = blockIdx.z;
    const float* W = (bz == 0) ? Wq : (bz == 1 ? Wk : Wv);
    float* O = (bz == 0) ? g_q : (bz == 1 ? g_k : g_v);

    const int row0 = blockIdx.x * 128;
    const int col0 = blockIdx.y * 128;
    const int tid  = threadIdx.x;
    const int warp = tid >> 5;
    const int lane = tid & 31;
    const int wm   = (warp >> 2) * 64;   // 0 or 64
    const int wn   = (warp & 3) * 32;    // 0,32,64,96
    const int g    = lane >> 2;          // 0..7
    const int t    = lane & 3;           // 0..3

    const int ar = tid >> 1;            // 0..127
    const int ae = (tid & 1) * 8;       // 0 or 8
    const int pk = (tid & 1) * 4;       // 0 or 4
    const int pr = tid >> 5;            // 0..7
    const int n4 = (tid & 31) * 4;      // 0..124

    const float* xp = x + (size_t)(row0 + ar) * D_ + ae;
    const float* wp = W + (size_t)(2 * pr) * NKH_ + col0 + n4;

    float acc[4][4][4];
    #pragma unroll
    for (int i = 0; i < 4; i++)
        #pragma unroll
        for (int j = 0; j < 4; j++)
            #pragma unroll
            for (int r = 0; r < 4; r++) acc[i][j][r] = 0.f;

    float4 av0 = *(const float4*)(xp);
    float4 av1 = *(const float4*)(xp + 4);
    float4 wv0 = *(const float4*)(wp);
    float4 wv1 = *(const float4*)(wp + NKH_);
    As2[0][pk + 0][ar] = splitpair(av0.x, av0.y);
    As2[0][pk + 1][ar] = splitpair(av0.z, av0.w);
    As2[0][pk + 2][ar] = splitpair(av1.x, av1.y);
    As2[0][pk + 3][ar] = splitpair(av1.z, av1.w);
    Bs2[0][pr][n4 + 0] = splitpair(wv0.x, wv1.x);
    Bs2[0][pr][n4 + 1] = splitpair(wv0.y, wv1.y);
    Bs2[0][pr][n4 + 2] = splitpair(wv0.z, wv1.z);
    Bs2[0][pr][n4 + 3] = splitpair(wv0.w, wv1.w);
    __syncthreads();

    int cur = 0;
    #pragma unroll 1
    for (int k0 = 16; k0 <= D_; k0 += 16) {
        if (k0 < D_) {
            av0 = *(const float4*)(xp + k0);
            av1 = *(const float4*)(xp + k0 + 4);
            wv0 = *(const float4*)(wp + (size_t)k0 * NKH_);
            wv1 = *(const float4*)(wp + (size_t)k0 * NKH_ + NKH_);
        }

        unsigned ahi[4][4], alo[4][4], bhi[4][2], blo[4][2];
        #pragma unroll
        for (int i = 0; i < 4; i++) {
            const int m0 = wm + i * 16 + g;
            uint2 p0 = As2[cur][t][m0];
            uint2 p1 = As2[cur][t][m0 + 8];
            uint2 p2 = As2[cur][t + 4][m0];
            uint2 p3 = As2[cur][t + 4][m0 + 8];
            ahi[i][0] = p0.x; alo[i][0] = p0.y;
            ahi[i][1] = p1.x; alo[i][1] = p1.y;
            ahi[i][2] = p2.x; alo[i][2] = p2.y;
            ahi[i][3] = p3.x; alo[i][3] = p3.y;
        }
        #pragma unroll
        for (int j = 0; j < 4; j++) {
            const int n0 = wn + j * 8 + g;
            uint2 q0 = Bs2[cur][t][n0];
            uint2 q1 = Bs2[cur][t + 4][n0];
            bhi[j][0] = q0.x; blo[j][0] = q0.y;
            bhi[j][1] = q1.x; blo[j][1] = q1.y;
        }
        // Term-major: 16 independent acc tiles between same-acc mmas
        #pragma unroll
        for (int i = 0; i < 4; i++)
            #pragma unroll
            for (int j = 0; j < 4; j++)
                mma_bf16(acc[i][j], ahi[i], bhi[j]);
        #pragma unroll
        for (int i = 0; i < 4; i++)
            #pragma unroll
            for (int j = 0; j < 4; j++)
                mma_bf16(acc[i][j], ahi[i], blo[j]);
        #pragma unroll
        for (int i = 0; i < 4; i++)
            #pragma unroll
            for (int j = 0; j < 4; j++)
                mma_bf16(acc[i][j], alo[i], bhi[j]);

        if (k0 < D_) {
            const int nxt = cur ^ 1;
            As2[nxt][pk + 0][ar] = splitpair(av0.x, av0.y);
            As2[nxt][pk + 1][ar] = splitpair(av0.z, av0.w);
            As2[nxt][pk + 2][ar] = splitpair(av1.x, av1.y);
            As2[nxt][pk + 3][ar] = splitpair(av1.z, av1.w);
            Bs2[nxt][pr][n4 + 0] = splitpair(wv0.x, wv1.x);
            Bs2[nxt][pr][n4 + 1] = splitpair(wv0.y, wv1.y);
            Bs2[nxt][pr][n4 + 2] = splitpair(wv0.z, wv1.z);
            Bs2[nxt][pr][n4 + 3] = splitpair(wv0.w, wv1.w);
            __syncthreads();
            cur = nxt;
        }
    }

    #pragma unroll
    for (int i = 0; i < 4; i++) {
        #pragma unroll
        for (int j = 0; j < 4; j++) {
            #pragma unroll
            for (int r = 0; r < 4; r++) {
                const int mrow = wm + i * 16 + g + ((r >= 2) ? 8 : 0);
                const int ncol = wn + j * 8 + 2 * t + (r & 1);
                const int rr = row0 + mrow;
                const int bb = rr >> 11;          // / S_
                const int s  = rr & (S_ - 1);
                const int c  = col0 + ncol;
                const int k  = c >> 4;            // / H_
                const int h  = c & (H_ - 1);
                O[((size_t)((bb * H_ + h) * S_ + s)) * KS_ + k] = acc[i][j][r];
            }
        }
    }
}

// ---------------------------------------------------------------------------
// Kernel 2: causal flash attention + FUSED output projection.
// 64 queries / CTA, 128 threads. QK^T: 1x tf32. PV: 3-term bf16, term-major.
// Epilogue: T = (P V) @ W_h on bf16 mma, atomicAdd into d_out.
// ---------------------------------------------------------------------------
#define KSTR 68
#define VSTR 72
__global__ __launch_bounds__(128) void attn_mma(
    const float* __restrict__ kern,
    float* __restrict__ out)
{
    __shared__ union {
        struct { float Ks[64][KSTR]; unsigned VhP[32][VSTR]; unsigned VlP[32][VSTR]; } m;
        struct { unsigned WhH[32][VSTR]; unsigned WhL[32][VSTR]; } e;
    } sm;   // 35.8 KB

    const int bh = blockIdx.x;                       // 0..31
    const int qt = (S_ / 64 - 1) - blockIdx.y;       // heavy tiles first
    const int i0 = qt * 64;
    const int tid  = threadIdx.x;
    const int warp = tid >> 5;
    const int lane = tid & 31;
    const int g = lane >> 2;   // 0..7
    const int t = lane & 3;    // 0..3

    const float* qb = g_q + (size_t)bh * S_ * KS_;
    const float* kb = g_k + (size_t)bh * S_ * KS_;
    const float* vb = g_v + (size_t)bh * S_ * KS_;

    const int qr = i0 + warp * 16;
    unsigned qf[8][4];
    #pragma unroll
    for (int ka = 0; ka < 8; ka++) {
        qf[ka][0] = f2tf32(qb[(size_t)(qr + g)     * KS_ + ka * 8 + t]     * 0.125f);
        qf[ka][1] = f2tf32(qb[(size_t)(qr + g + 8) * KS_ + ka * 8 + t]     * 0.125f);
        qf[ka][2] = f2tf32(qb[(size_t)(qr + g)     * KS_ + ka * 8 + t + 4] * 0.125f);
        qf[ka][3] = f2tf32(qb[(size_t)(qr + g + 8) * KS_ + ka * 8 + t + 4] * 0.125f);
    }

    float acc[8][4];
    #pragma unroll
    for (int n = 0; n < 8; n++)
        #pragma unroll
        for (int r = 0; r < 4; r++) acc[n][r] = 0.f;
    float m0 = -1e30f, m1 = -1e30f, l0 = 0.f, l1 = 0.f;

    for (int j0 = 0; j0 <= i0; j0 += 64) {
        __syncthreads();
        const float4* kt = (const float4*)(kb + (size_t)j0 * KS_);
        const float4* vt = (const float4*)(vb + (size_t)j0 * KS_);
        // K: 1024 float4s, tf32-converted
        #pragma unroll
        for (int u = 0; u < 8; u++) {
            const int f = tid + u * 128;
            const int key = f >> 4;
            const int d4  = (f & 15) * 4;
            float4 kv = kt[f];
            *(float4*)&sm.m.Ks[key][d4] =
                make_float4(tf32f(kv.x), tf32f(kv.y), tf32f(kv.z), tf32f(kv.w));
        }
        // V: 512 key-pair tasks -> packed bf16 hi/lo planes
        #pragma unroll
        for (int u = 0; u < 4; u++) {
            const int f  = tid + u * 128;    // 0..511
            const int kp = f >> 4;           // 0..31
            const int d4 = (f & 15) * 4;
            float4 v0 = vt[(2 * kp) * 16 + (f & 15)];
            float4 v1 = vt[(2 * kp + 1) * 16 + (f & 15)];
            uint2 pa = splitpair(v0.x, v1.x);
            uint2 pb = splitpair(v0.y, v1.y);
            uint2 pc = splitpair(v0.z, v1.z);
            uint2 pd = splitpair(v0.w, v1.w);
            *(uint4*)&sm.m.VhP[kp][d4] = make_uint4(pa.x, pb.x, pc.x, pd.x);
            *(uint4*)&sm.m.VlP[kp][d4] = make_uint4(pa.y, pb.y, pc.y, pd.y);
        }
        __syncthreads();

        // ---- scores: S(16x64) = Q K^T ----
        float c[8][4];
        #pragma unroll
        for (int n = 0; n < 8; n++)
            #pragma unroll
            for (int r = 0; r < 4; r++) c[n][r] = 0.f;

        #pragma unroll
        for (int ka = 0; ka < 8; ka++) {
            #pragma unroll
            for (int n = 0; n < 8; n++) {
                unsigned b[2];
                b[0] = __float_as_uint(sm.m.Ks[n * 8 + g][ka * 8 + t]);
                b[1] = __float_as_uint(sm.m.Ks[n * 8 + g][ka * 8 + t + 4]);
                mma_tf32(c[n], qf[ka], b);
            }
        }

        // ---- causal mask (diagonal tile only) ----
        if (j0 == i0) {
            const int r0 = qr + g;
            const int r1 = r0 + 8;
            #pragma unroll
            for (int n = 0; n < 8; n++) {
                const int k0c = j0 + n * 8 + 2 * t;
                if (k0c     > r0) c[n][0] = -1e30f;
                if (k0c + 1 > r0) c[n][1] = -1e30f;
                if (k0c     > r1) c[n][2] = -1e30f;
                if (k0c + 1 > r1) c[n][3] = -1e30f;
            }
        }

        // ---- online softmax (rows g and g+8) ----
        float t0 = -1e30f, t1 = -1e30f;
        #pragma unroll
        for (int n = 0; n < 8; n++) {
            t0 = fmaxf(t0, fmaxf(c[n][0], c[n][1]));
            t1 = fmaxf(t1, fmaxf(c[n][2], c[n][3]));
        }
        t0 = fmaxf(t0, __shfl_xor_sync(0xffffffffu, t0, 1));
        t0 = fmaxf(t0, __shfl_xor_sync(0xffffffffu, t0, 2));
        t1 = fmaxf(t1, __shfl_xor_sync(0xffffffffu, t1, 1));
        t1 = fmaxf(t1, __shfl_xor_sync(0xffffffffu, t1, 2));
        const float nm0 = fmaxf(m0, t0);
        const float nm1 = fmaxf(m1, t1);
        const float f0 = __expf(m0 - nm0);
        const float f1 = __expf(m1 - nm1);
        m0 = nm0; m1 = nm1;
        l0 *= f0;  l1 *= f1;
        #pragma unroll
        for (int n = 0; n < 8; n++) {
            acc[n][0] *= f0; acc[n][1] *= f0;
            acc[n][2] *= f1; acc[n][3] *= f1;
        }
        float ps0 = 0.f, ps1 = 0.f;
        #pragma unroll
        for (int n = 0; n < 8; n++) {
            c[n][0] = __expf(c[n][0] - m0);
            c[n][1] = __expf(c[n][1] - m0);
            c[n][2] = __expf(c[n][2] - m1);
            c[n][3] = __expf(c[n][3] - m1);
            ps0 += c[n][0] + c[n][1];
            ps1 += c[n][2] + c[n][3];
        }
        ps0 += __shfl_xor_sync(0xffffffffu, ps0, 1);
        ps0 += __shfl_xor_sync(0xffffffffu, ps0, 2);
        ps1 += __shfl_xor_sync(0xffffffffu, ps1, 1);
        ps1 += __shfl_xor_sync(0xffffffffu, ps1, 2);
        l0 += ps0; l1 += ps1;

        // ---- PV: acc += P V (bf16 3-term, term-major per ka) ----
        #pragma unroll
        for (int ka = 0; ka < 4; ka++) {
            unsigned ahi[4], alo[4];
            uint2 p;
            p = splitpair(c[2*ka][0],     c[2*ka][1]);     ahi[0] = p.x; alo[0] = p.y;
            p = splitpair(c[2*ka][2],     c[2*ka][3]);     ahi[1] = p.x; alo[1] = p.y;
            p = splitpair(c[2*ka+1][0],   c[2*ka+1][1]);   ahi[2] = p.x; alo[2] = p.y;
            p = splitpair(c[2*ka+1][2],   c[2*ka+1][3]);   ahi[3] = p.x; alo[3] = p.y;
            unsigned bh2[8][2], bl2[8][2];
            #pragma unroll
            for (int n = 0; n < 8; n++) {
                bh2[n][0] = sm.m.VhP[ka * 8 + t][n * 8 + g];
                bh2[n][1] = sm.m.VhP[ka * 8 + t + 4][n * 8 + g];
                bl2[n][0] = sm.m.VlP[ka * 8 + t][n * 8 + g];
                bl2[n][1] = sm.m.VlP[ka * 8 + t + 4][n * 8 + g];
            }
            #pragma unroll
            for (int n = 0; n < 8; n++) mma_bf16(acc[n], ahi, bh2[n]);
            #pragma unroll
            for (int n = 0; n < 8; n++) mma_bf16(acc[n], ahi, bl2[n]);
            #pragma unroll
            for (int n = 0; n < 8; n++) mma_bf16(acc[n], alo, bh2[n]);
        }
    }

    // ================= FUSED OUTPUT PROJECTION =================
    const float inv0 = 1.f / l0;
    const float inv1 = 1.f / l1;
    const int bb = bh >> 4;        // / H_
    const int h  = bh & (H_ - 1);

    __syncthreads();
    #pragma unroll
    for (int u = 0; u < 16; u++) {
        const int f  = tid + u * 128;    // 0..2047
        const int kp = f >> 6;           // 0..31
        const int j  = f & 63;
        const float e0 = kern[((size_t)(2 * kp)     * H_ + h) * KS_ + j];
        const float e1 = kern[((size_t)(2 * kp + 1) * H_ + h) * KS_ + j];
        uint2 p = splitpair(e0, e1);
        sm.e.WhH[kp][j] = p.x;
        sm.e.WhL[kp][j] = p.y;
    }
    __syncthreads();

    // T(16x64) = normalized(P V) @ W_h — term-major per ka
    float o[8][4];
    #pragma unroll
    for (int n = 0; n < 8; n++)
        #pragma unroll
        for (int r = 0; r < 4; r++) o[n][r] = 0.f;

    #pragma unroll
    for (int ka = 0; ka < 4; ka++) {
        unsigned ahi[4], alo[4];
        uint2 p;
        p = splitpair(acc[2*ka][0]   * inv0, acc[2*ka][1]   * inv0); ahi[0] = p.x; alo[0] = p.y;
        p = splitpair(acc[2*ka][2]   * inv1, acc[2*ka][3]   * inv1); ahi[1] = p.x; alo[1] = p.y;
        p = splitpair(acc[2*ka+1][0] * inv0, acc[2*ka+1][1] * inv0); ahi[2] = p.x; alo[2] = p.y;
        p = splitpair(acc[2*ka+1][2] * inv1, acc[2*ka+1][3] * inv1); ahi[3] = p.x; alo[3] = p.y;
        unsigned bh2[8][2], bl2[8][2];
        #pragma unroll
        for (int n = 0; n < 8; n++) {
            bh2[n][0] = sm.e.WhH[ka * 8 + t][n * 8 + g];
            bh2[n][1] = sm.e.WhH[ka * 8 + t + 4][n * 8 + g];
            bl2[n][0] = sm.e.WhL[ka * 8 + t][n * 8 + g];
            bl2[n][1] = sm.e.WhL[ka * 8 + t + 4][n * 8 + g];
        }
        #pragma unroll
        for (int n = 0; n < 8; n++) mma_bf16(o[n], ahi, bh2[n]);
        #pragma unroll
        for (int n = 0; n < 8; n++) mma_bf16(o[n], ahi, bl2[n]);
        #pragma unroll
        for (int n = 0; n < 8; n++) mma_bf16(o[n], alo, bh2[n]);
    }

    // Accumulate into d_out
    float* or0 = out + (size_t)(bb * S_ + qr + g) * KS_;
    float* or1 = out + (size_t)(bb * S_ + qr + g + 8) * KS_;
    #pragma unroll
    for (int n = 0; n < 8; n++) {
        const int jc = n * 8 + 2 * t;
        atomicAdd(&or0[jc],     o[n][0]);
        atomicAdd(&or0[jc + 1], o[n][1]);
        atomicAdd(&or1[jc],     o[n][2]);
        atomicAdd(&or1[jc + 1], o[n][3]);
    }
}

// ---------------------------------------------------------------------------
// Kernel 3: zero d_out (poisoned by harness; attn accumulates into it).
// ---------------------------------------------------------------------------
__global__ __launch_bounds__(256) void zero_out(float* __restrict__ out)
{
    out[blockIdx.x * 256 + threadIdx.x] = 0.f;
}

// ---------------------------------------------------------------------------
extern "C" void kernel_launch(void* const* d_in, const int* in_sizes, int n_in,
                              void* d_out, int out_size)
{
    (void)in_sizes; (void)n_in; (void)out_size;
    const float* x  = (const float*)d_in[0];
    const float* Wq = (const float*)d_in[1];
    const float* Wk = (const float*)d_in[2];
    const float* Wv = (const float*)d_in[3];
    const float* kr = (const float*)d_in[4];
    float* out = (float*)d_out;

    zero_out<<<(B_ * S_ * KS_) / 256, 256>>>(out);

    dim3 g1(B_ * S_ / 128, NKH_ / 128, 3);   // (32, 8, 3)
    qkv_gemm<<<g1, 256>>>(x, Wq, Wk, Wv);

    dim3 g2(NBH_, S_ / 64);                  // (32, 32)
    attn_mma<<<g2, 128>>>(kr, out);
}

// round 16
// speedup vs baseline: 1.4249x; 1.4249x over previous
#include <cuda_runtime.h>

// Problem dims (fixed)
#define B_   2
#define S_   2048
#define D_   1024
#define H_   16
#define KS_  64
#define NKH_ (KS_ * H_)   // 1024
#define NBH_ (B_ * H_)    // 32

// Device scratch (allocation-free rule: device globals)
__device__ float g_q[NBH_ * S_ * KS_];      // [b,h,s,k]
__device__ float g_k[NBH_ * S_ * KS_];
__device__ float g_v[NBH_ * S_ * KS_];

// ---------------------------------------------------------------------------
// TF32 helpers
// ---------------------------------------------------------------------------
__device__ __forceinline__ unsigned f2tf32(float f) {
    unsigned r;
    asm("cvt.rna.tf32.f32 %0, %1;" : "=r"(r) : "f"(f));
    return r;
}
__device__ __forceinline__ float tf32f(float f) {
    return __uint_as_float(f2tf32(f));
}
__device__ __forceinline__ void mma_tf32(float* c, const unsigned* a, const unsigned* b) {
    asm volatile(
        "mma.sync.aligned.m16n8k8.row.col.f32.tf32.tf32.f32 "
        "{%0,%1,%2,%3}, {%4,%5,%6,%7}, {%8,%9}, {%0,%1,%2,%3};"
        : "+f"(c[0]), "+f"(c[1]), "+f"(c[2]), "+f"(c[3])
        : "r"(a[0]), "r"(a[1]), "r"(a[2]), "r"(a[3]), "r"(b[0]), "r"(b[1]));
}

// ---------------------------------------------------------------------------
// BF16 helpers: 3-term split (hi*hi + hi*lo + lo*hi)
// ---------------------------------------------------------------------------
__device__ __forceinline__ unsigned bf16pack(float lo, float hi) {
    unsigned r;
    asm("cvt.rn.bf16x2.f32 %0, %1, %2;" : "=r"(r) : "f"(hi), "f"(lo));
    return r;
}
__device__ __forceinline__ float bf16lo_f(unsigned p) { return __uint_as_float(p << 16); }
__device__ __forceinline__ float bf16hi_f(unsigned p) { return __uint_as_float(p & 0xffff0000u); }
__device__ __forceinline__ uint2 splitpair(float e0, float e1) {
    unsigned h = bf16pack(e0, e1);
    float r0 = e0 - bf16lo_f(h);
    float r1 = e1 - bf16hi_f(h);
    unsigned l = bf16pack(r0, r1);
    return make_uint2(h, l);
}
__device__ __forceinline__ void mma_bf16(float* c, const unsigned* a, const unsigned* b) {
    asm volatile(
        "mma.sync.aligned.m16n8k16.row.col.f32.bf16.bf16.f32 "
        "{%0,%1,%2,%3}, {%4,%5,%6,%7}, {%8,%9}, {%0,%1,%2,%3};"
        : "+f"(c[0]), "+f"(c[1]), "+f"(c[2]), "+f"(c[3])
        : "r"(a[0]), "r"(a[1]), "r"(a[2]), "r"(a[3]), "r"(b[0]), "r"(b[1]));
}

// ---------------------------------------------------------------------------
// Kernel 1: QKV projection GEMM, 3x-split bf16 m16n8k16, split-at-staging.
// (R8/R14 interleaved mma order — register-lifetime friendly.)
// ---------------------------------------------------------------------------
__global__ __launch_bounds__(256, 2) void qkv_gemm(
    const float* __restrict__ x,
    const float* __restrict__ Wq,
    const float* __restrict__ Wk,
    const float* __restrict__ Wv)
{
    __shared__ uint2 As2[2][8][132];   // 16.9 KB
    __shared__ uint2 Bs2[2][8][132];   // 16.9 KB

    const int bz = blockIdx.z;
    const float* W = (bz == 0) ? Wq : (bz == 1 ? Wk : Wv);
    float* O = (bz == 0) ? g_q : (bz == 1 ? g_k : g_v);

    const int row0 = blockIdx.x * 128;
    const int col0 = blockIdx.y * 128;
    const int tid  = threadIdx.x;
    const int warp = tid >> 5;
    const int lane = tid & 31;
    const int wm   = (warp >> 2) * 64;   // 0 or 64
    const int wn   = (warp & 3) * 32;    // 0,32,64,96
    const int g    = lane >> 2;          // 0..7
    const int t    = lane & 3;           // 0..3

    const int ar = tid >> 1;            // 0..127
    const int ae = (tid & 1) * 8;       // 0 or 8
    const int pk = (tid & 1) * 4;       // 0 or 4
    const int pr = tid >> 5;            // 0..7
    const int n4 = (tid & 31) * 4;      // 0..124

    const float* xp = x + (size_t)(row0 + ar) * D_ + ae;
    const float* wp = W + (size_t)(2 * pr) * NKH_ + col0 + n4;

    float acc[4][4][4];
    #pragma unroll
    for (int i = 0; i < 4; i++)
        #pragma unroll
        for (int j = 0; j < 4; j++)
            #pragma unroll
            for (int r = 0; r < 4; r++) acc[i][j][r] = 0.f;

    float4 av0 = *(const float4*)(xp);
    float4 av1 = *(const float4*)(xp + 4);
    float4 wv0 = *(const float4*)(wp);
    float4 wv1 = *(const float4*)(wp + NKH_);
    As2[0][pk + 0][ar] = splitpair(av0.x, av0.y);
    As2[0][pk + 1][ar] = splitpair(av0.z, av0.w);
    As2[0][pk + 2][ar] = splitpair(av1.x, av1.y);
    As2[0][pk + 3][ar] = splitpair(av1.z, av1.w);
    Bs2[0][pr][n4 + 0] = splitpair(wv0.x, wv1.x);
    Bs2[0][pr][n4 + 1] = splitpair(wv0.y, wv1.y);
    Bs2[0][pr][n4 + 2] = splitpair(wv0.z, wv1.z);
    Bs2[0][pr][n4 + 3] = splitpair(wv0.w, wv1.w);
    __syncthreads();

    int cur = 0;
    #pragma unroll 1
    for (int k0 = 16; k0 <= D_; k0 += 16) {
        if (k0 < D_) {
            av0 = *(const float4*)(xp + k0);
            av1 = *(const float4*)(xp + k0 + 4);
            wv0 = *(const float4*)(wp + (size_t)k0 * NKH_);
            wv1 = *(const float4*)(wp + (size_t)k0 * NKH_ + NKH_);
        }

        unsigned ahi[4][4], alo[4][4], bhi[4][2], blo[4][2];
        #pragma unroll
        for (int i = 0; i < 4; i++) {
            const int m0 = wm + i * 16 + g;
            uint2 p0 = As2[cur][t][m0];
            uint2 p1 = As2[cur][t][m0 + 8];
            uint2 p2 = As2[cur][t + 4][m0];
            uint2 p3 = As2[cur][t + 4][m0 + 8];
            ahi[i][0] = p0.x; alo[i][0] = p0.y;
            ahi[i][1] = p1.x; alo[i][1] = p1.y;
            ahi[i][2] = p2.x; alo[i][2] = p2.y;
            ahi[i][3] = p3.x; alo[i][3] = p3.y;
        }
        #pragma unroll
        for (int j = 0; j < 4; j++) {
            const int n0 = wn + j * 8 + g;
            uint2 q0 = Bs2[cur][t][n0];
            uint2 q1 = Bs2[cur][t + 4][n0];
            bhi[j][0] = q0.x; blo[j][0] = q0.y;
            bhi[j][1] = q1.x; blo[j][1] = q1.y;
        }
        #pragma unroll
        for (int i = 0; i < 4; i++)
            #pragma unroll
            for (int j = 0; j < 4; j++) {
                mma_bf16(acc[i][j], ahi[i], bhi[j]);
                mma_bf16(acc[i][j], ahi[i], blo[j]);
                mma_bf16(acc[i][j], alo[i], bhi[j]);
            }

        if (k0 < D_) {
            const int nxt = cur ^ 1;
            As2[nxt][pk + 0][ar] = splitpair(av0.x, av0.y);
            As2[nxt][pk + 1][ar] = splitpair(av0.z, av0.w);
            As2[nxt][pk + 2][ar] = splitpair(av1.x, av1.y);
            As2[nxt][pk + 3][ar] = splitpair(av1.z, av1.w);
            Bs2[nxt][pr][n4 + 0] = splitpair(wv0.x, wv1.x);
            Bs2[nxt][pr][n4 + 1] = splitpair(wv0.y, wv1.y);
            Bs2[nxt][pr][n4 + 2] = splitpair(wv0.z, wv1.z);
            Bs2[nxt][pr][n4 + 3] = splitpair(wv0.w, wv1.w);
            __syncthreads();
            cur = nxt;
        }
    }

    #pragma unroll
    for (int i = 0; i < 4; i++) {
        #pragma unroll
        for (int j = 0; j < 4; j++) {
            #pragma unroll
            for (int r = 0; r < 4; r++) {
                const int mrow = wm + i * 16 + g + ((r >= 2) ? 8 : 0);
                const int ncol = wn + j * 8 + 2 * t + (r & 1);
                const int rr = row0 + mrow;
                const int bb = rr >> 11;          // / S_
                const int s  = rr & (S_ - 1);
                const int c  = col0 + ncol;
                const int k  = c >> 4;            // / H_
                const int h  = c & (H_ - 1);
                O[((size_t)((bb * H_ + h) * S_ + s)) * KS_ + k] = acc[i][j][r];
            }
        }
    }
}

// ---------------------------------------------------------------------------
// Kernel 2: causal flash attention + FUSED output projection. (R14 version)
// 64 queries / CTA, 128 threads. QK^T: 1x tf32. PV: 3-term bf16.
// Epilogue: T = (P V) @ W_h on bf16 mma, atomicAdd into d_out.
// ---------------------------------------------------------------------------
#define KSTR 68
#define VSTR 72
__global__ __launch_bounds__(128) void attn_mma(
    const float* __restrict__ kern,
    float* __restrict__ out)
{
    __shared__ union {
        struct { float Ks[64][KSTR]; unsigned VhP[32][VSTR]; unsigned VlP[32][VSTR]; } m;
        struct { unsigned WhH[32][VSTR]; unsigned WhL[32][VSTR]; } e;
    } sm;   // 35.8 KB

    const int bh = blockIdx.x;                       // 0..31
    const int qt = (S_ / 64 - 1) - blockIdx.y;       // heavy tiles first
    const int i0 = qt * 64;
    const int tid  = threadIdx.x;
    const int warp = tid >> 5;
    const int lane = tid & 31;
    const int g = lane >> 2;   // 0..7
    const int t = lane & 3;    // 0..3

    const float* qb = g_q + (size_t)bh * S_ * KS_;
    const float* kb = g_k + (size_t)bh * S_ * KS_;
    const float* vb = g_v + (size_t)bh * S_ * KS_;

    const int qr = i0 + warp * 16;
    unsigned qf[8][4];
    #pragma unroll
    for (int ka = 0; ka < 8; ka++) {
        qf[ka][0] = f2tf32(qb[(size_t)(qr + g)     * KS_ + ka * 8 + t]     * 0.125f);
        qf[ka][1] = f2tf32(qb[(size_t)(qr + g + 8) * KS_ + ka * 8 + t]     * 0.125f);
        qf[ka][2] = f2tf32(qb[(size_t)(qr + g)     * KS_ + ka * 8 + t + 4] * 0.125f);
        qf[ka][3] = f2tf32(qb[(size_t)(qr + g + 8) * KS_ + ka * 8 + t + 4] * 0.125f);
    }

    float acc[8][4];
    #pragma unroll
    for (int n = 0; n < 8; n++)
        #pragma unroll
        for (int r = 0; r < 4; r++) acc[n][r] = 0.f;
    float m0 = -1e30f, m1 = -1e30f, l0 = 0.f, l1 = 0.f;

    for (int j0 = 0; j0 <= i0; j0 += 64) {
        __syncthreads();
        const float4* kt = (const float4*)(kb + (size_t)j0 * KS_);
        const float4* vt = (const float4*)(vb + (size_t)j0 * KS_);
        // K: 1024 float4s, tf32-converted
        #pragma unroll
        for (int u = 0; u < 8; u++) {
            const int f = tid + u * 128;
            const int key = f >> 4;
            const int d4  = (f & 15) * 4;
            float4 kv = kt[f];
            *(float4*)&sm.m.Ks[key][d4] =
                make_float4(tf32f(kv.x), tf32f(kv.y), tf32f(kv.z), tf32f(kv.w));
        }
        // V: 512 key-pair tasks -> packed bf16 hi/lo planes
        #pragma unroll
        for (int u = 0; u < 4; u++) {
            const int f  = tid + u * 128;    // 0..511
            const int kp = f >> 4;           // 0..31
            const int d4 = (f & 15) * 4;
            float4 v0 = vt[(2 * kp) * 16 + (f & 15)];
            float4 v1 = vt[(2 * kp + 1) * 16 + (f & 15)];
            uint2 pa = splitpair(v0.x, v1.x);
            uint2 pb = splitpair(v0.y, v1.y);
            uint2 pc = splitpair(v0.z, v1.z);
            uint2 pd = splitpair(v0.w, v1.w);
            *(uint4*)&sm.m.VhP[kp][d4] = make_uint4(pa.x, pb.x, pc.x, pd.x);
            *(uint4*)&sm.m.VlP[kp][d4] = make_uint4(pa.y, pb.y, pc.y, pd.y);
        }
        __syncthreads();

        // ---- scores: S(16x64) = Q K^T ----
        float c[8][4];
        #pragma unroll
        for (int n = 0; n < 8; n++)
            #pragma unroll
            for (int r = 0; r < 4; r++) c[n][r] = 0.f;

        #pragma unroll
        for (int ka = 0; ka < 8; ka++) {
            #pragma unroll
            for (int n = 0; n < 8; n++) {
                unsigned b[2];
                b[0] = __float_as_uint(sm.m.Ks[n * 8 + g][ka * 8 + t]);
                b[1] = __float_as_uint(sm.m.Ks[n * 8 + g][ka * 8 + t + 4]);
                mma_tf32(c[n], qf[ka], b);
            }
        }

        // ---- causal mask (diagonal tile only) ----
        if (j0 == i0) {
            const int r0 = qr + g;
            const int r1 = r0 + 8;
            #pragma unroll
            for (int n = 0; n < 8; n++) {
                const int k0c = j0 + n * 8 + 2 * t;
                if (k0c     > r0) c[n][0] = -1e30f;
                if (k0c + 1 > r0) c[n][1] = -1e30f;
                if (k0c     > r1) c[n][2] = -1e30f;
                if (k0c + 1 > r1) c[n][3] = -1e30f;
            }
        }

        // ---- online softmax (rows g and g+8) ----
        float t0 = -1e30f, t1 = -1e30f;
        #pragma unroll
        for (int n = 0; n < 8; n++) {
            t0 = fmaxf(t0, fmaxf(c[n][0], c[n][1]));
            t1 = fmaxf(t1, fmaxf(c[n][2], c[n][3]));
        }
        t0 = fmaxf(t0, __shfl_xor_sync(0xffffffffu, t0, 1));
        t0 = fmaxf(t0, __shfl_xor_sync(0xffffffffu, t0, 2));
        t1 = fmaxf(t1, __shfl_xor_sync(0xffffffffu, t1, 1));
        t1 = fmaxf(t1, __shfl_xor_sync(0xffffffffu, t1, 2));
        const float nm0 = fmaxf(m0, t0);
        const float nm1 = fmaxf(m1, t1);
        const float f0 = __expf(m0 - nm0);
        const float f1 = __expf(m1 - nm1);
        m0 = nm0; m1 = nm1;
        l0 *= f0;  l1 *= f1;
        #pragma unroll
        for (int n = 0; n < 8; n++) {
            acc[n][0] *= f0; acc[n][1] *= f0;
            acc[n][2] *= f1; acc[n][3] *= f1;
        }
        float ps0 = 0.f, ps1 = 0.f;
        #pragma unroll
        for (int n = 0; n < 8; n++) {
            c[n][0] = __expf(c[n][0] - m0);
            c[n][1] = __expf(c[n][1] - m0);
            c[n][2] = __expf(c[n][2] - m1);
            c[n][3] = __expf(c[n][3] - m1);
            ps0 += c[n][0] + c[n][1];
            ps1 += c[n][2] + c[n][3];
        }
        ps0 += __shfl_xor_sync(0xffffffffu, ps0, 1);
        ps0 += __shfl_xor_sync(0xffffffffu, ps0, 2);
        ps1 += __shfl_xor_sync(0xffffffffu, ps1, 1);
        ps1 += __shfl_xor_sync(0xffffffffu, ps1, 2);
        l0 += ps0; l1 += ps1;

        // ---- PV: acc += P V (bf16 3-term, interleaved order) ----
        #pragma unroll
        for (int ka = 0; ka < 4; ka++) {
            unsigned ahi[4], alo[4];
            uint2 p;
            p = splitpair(c[2*ka][0],     c[2*ka][1]);     ahi[0] = p.x; alo[0] = p.y;
            p = splitpair(c[2*ka][2],     c[2*ka][3]);     ahi[1] = p.x; alo[1] = p.y;
            p = splitpair(c[2*ka+1][0],   c[2*ka+1][1]);   ahi[2] = p.x; alo[2] = p.y;
            p = splitpair(c[2*ka+1][2],   c[2*ka+1][3]);   ahi[3] = p.x; alo[3] = p.y;
            #pragma unroll
            for (int n = 0; n < 8; n++) {
                unsigned bh2[2], bl2[2];
                bh2[0] = sm.m.VhP[ka * 8 + t][n * 8 + g];
                bh2[1] = sm.m.VhP[ka * 8 + t + 4][n * 8 + g];
                bl2[0] = sm.m.VlP[ka * 8 + t][n * 8 + g];
                bl2[1] = sm.m.VlP[ka * 8 + t + 4][n * 8 + g];
                mma_bf16(acc[n], ahi, bh2);
                mma_bf16(acc[n], ahi, bl2);
                mma_bf16(acc[n], alo, bh2);
            }
        }
    }

    // ================= FUSED OUTPUT PROJECTION =================
    const float inv0 = 1.f / l0;
    const float inv1 = 1.f / l1;
    const int bb = bh >> 4;        // / H_
    const int h  = bh & (H_ - 1);

    __syncthreads();
    #pragma unroll
    for (int u = 0; u < 16; u++) {
        const int f  = tid + u * 128;    // 0..2047
        const int kp = f >> 6;           // 0..31
        const int j  = f & 63;
        const float e0 = kern[((size_t)(2 * kp)     * H_ + h) * KS_ + j];
        const float e1 = kern[((size_t)(2 * kp + 1) * H_ + h) * KS_ + j];
        uint2 p = splitpair(e0, e1);
        sm.e.WhH[kp][j] = p.x;
        sm.e.WhL[kp][j] = p.y;
    }
    __syncthreads();

    // T(16x64) = normalized(P V) @ W_h  — same fragment mapping as PV
    float o[8][4];
    #pragma unroll
    for (int n = 0; n < 8; n++)
        #pragma unroll
        for (int r = 0; r < 4; r++) o[n][r] = 0.f;

    #pragma unroll
    for (int ka = 0; ka < 4; ka++) {
        unsigned ahi[4], alo[4];
        uint2 p;
        p = splitpair(acc[2*ka][0]   * inv0, acc[2*ka][1]   * inv0); ahi[0] = p.x; alo[0] = p.y;
        p = splitpair(acc[2*ka][2]   * inv1, acc[2*ka][3]   * inv1); ahi[1] = p.x; alo[1] = p.y;
        p = splitpair(acc[2*ka+1][0] * inv0, acc[2*ka+1][1] * inv0); ahi[2] = p.x; alo[2] = p.y;
        p = splitpair(acc[2*ka+1][2] * inv1, acc[2*ka+1][3] * inv1); ahi[3] = p.x; alo[3] = p.y;
        #pragma unroll
        for (int n = 0; n < 8; n++) {
            unsigned bh2[2], bl2[2];
            bh2[0] = sm.e.WhH[ka * 8 + t][n * 8 + g];
            bh2[1] = sm.e.WhH[ka * 8 + t + 4][n * 8 + g];
            bl2[0] = sm.e.WhL[ka * 8 + t][n * 8 + g];
            bl2[1] = sm.e.WhL[ka * 8 + t + 4][n * 8 + g];
            mma_bf16(o[n], ahi, bh2);
            mma_bf16(o[n], ahi, bl2);
            mma_bf16(o[n], alo, bh2);
        }
    }

    // Accumulate into d_out (rows bb*S + qr+g / +8, cols n*8+2t..+1)
    float* or0 = out + (size_t)(bb * S_ + qr + g) * KS_;
    float* or1 = out + (size_t)(bb * S_ + qr + g + 8) * KS_;
    #pragma unroll
    for (int n = 0; n < 8; n++) {
        const int jc = n * 8 + 2 * t;
        atomicAdd(&or0[jc],     o[n][0]);
        atomicAdd(&or0[jc + 1], o[n][1]);
        atomicAdd(&or1[jc],     o[n][2]);
        atomicAdd(&or1[jc + 1], o[n][3]);
    }
}

// ---------------------------------------------------------------------------
// Kernel 3: zero d_out (poisoned by harness; attn accumulates into it).
// float4 stores, 256 blocks.
// ---------------------------------------------------------------------------
__global__ __launch_bounds__(256) void zero_out(float4* __restrict__ out)
{
    out[blockIdx.x * 256 + threadIdx.x] = make_float4(0.f, 0.f, 0.f, 0.f);
}

// ---------------------------------------------------------------------------
extern "C" void kernel_launch(void* const* d_in, const int* in_sizes, int n_in,
                              void* d_out, int out_size)
{
    (void)in_sizes; (void)n_in; (void)out_size;
    const float* x  = (const float*)d_in[0];
    const float* Wq = (const float*)d_in[1];
    const float* Wk = (const float*)d_in[2];
    const float* Wv = (const float*)d_in[3];
    const float* kr = (const float*)d_in[4];
    float* out = (float*)d_out;

    zero_out<<<(B_ * S_ * KS_) / 1024, 256>>>((float4*)out);

    dim3 g1(B_ * S_ / 128, NKH_ / 128, 3);   // (32, 8, 3)
    qkv_gemm<<<g1, 256>>>(x, Wq, Wk, Wv);

    dim3 g2(NBH_, S_ / 64);                  // (32, 32)
    attn_mma<<<g2, 128>>>(kr, out);
}

// round 17
// speedup vs baseline: 1.5024x; 1.0544x over previous
#include <cuda_runtime.h>

// Problem dims (fixed)
#define B_   2
#define S_   2048
#define D_   1024
#define H_   16
#define KS_  64
#define NKH_ (KS_ * H_)   // 1024
#define NBH_ (B_ * H_)    // 32

// Device scratch (allocation-free rule: device globals)
__device__ float g_q[NBH_ * S_ * KS_];      // [b,h,s,k]
__device__ float g_k[NBH_ * S_ * KS_];
__device__ float g_v[NBH_ * S_ * KS_];

// ---------------------------------------------------------------------------
// TF32 helpers
// ---------------------------------------------------------------------------
__device__ __forceinline__ unsigned f2tf32(float f) {
    unsigned r;
    asm("cvt.rna.tf32.f32 %0, %1;" : "=r"(r) : "f"(f));
    return r;
}
__device__ __forceinline__ float tf32f(float f) {
    return __uint_as_float(f2tf32(f));
}
__device__ __forceinline__ void mma_tf32(float* c, const unsigned* a, const unsigned* b) {
    asm volatile(
        "mma.sync.aligned.m16n8k8.row.col.f32.tf32.tf32.f32 "
        "{%0,%1,%2,%3}, {%4,%5,%6,%7}, {%8,%9}, {%0,%1,%2,%3};"
        : "+f"(c[0]), "+f"(c[1]), "+f"(c[2]), "+f"(c[3])
        : "r"(a[0]), "r"(a[1]), "r"(a[2]), "r"(a[3]), "r"(b[0]), "r"(b[1]));
}

// ---------------------------------------------------------------------------
// BF16 helpers: 3-term split (hi*hi + hi*lo + lo*hi)
// ---------------------------------------------------------------------------
__device__ __forceinline__ unsigned bf16pack(float lo, float hi) {
    unsigned r;
    asm("cvt.rn.bf16x2.f32 %0, %1, %2;" : "=r"(r) : "f"(hi), "f"(lo));
    return r;
}
__device__ __forceinline__ float bf16lo_f(unsigned p) { return __uint_as_float(p << 16); }
__device__ __forceinline__ float bf16hi_f(unsigned p) { return __uint_as_float(p & 0xffff0000u); }
__device__ __forceinline__ uint2 splitpair(float e0, float e1) {
    unsigned h = bf16pack(e0, e1);
    float r0 = e0 - bf16lo_f(h);
    float r1 = e1 - bf16hi_f(h);
    unsigned l = bf16pack(r0, r1);
    return make_uint2(h, l);
}
__device__ __forceinline__ void mma_bf16(float* c, const unsigned* a, const unsigned* b) {
    asm volatile(
        "mma.sync.aligned.m16n8k16.row.col.f32.bf16.bf16.f32 "
        "{%0,%1,%2,%3}, {%4,%5,%6,%7}, {%8,%9}, {%0,%1,%2,%3};"
        : "+f"(c[0]), "+f"(c[1]), "+f"(c[2]), "+f"(c[3])
        : "r"(a[0]), "r"(a[1]), "r"(a[2]), "r"(a[3]), "r"(b[0]), "r"(b[1]));
}

// ---------------------------------------------------------------------------
// Kernel 1: QKV projection GEMM, 3x-split bf16 m16n8k16, split-at-staging.
// Mainloop identical to best baseline. Epilogue: smem-staged coalesced stores.
// ---------------------------------------------------------------------------
__global__ __launch_bounds__(256, 2) void qkv_gemm(
    const float* __restrict__ x,
    const float* __restrict__ Wq,
    const float* __restrict__ Wk,
    const float* __restrict__ Wv)
{
    // Raw smem carved into mainloop buffers; reused by the epilogue staging.
    __shared__ __align__(16) char smraw[2 * 16896];
    typedef uint2 (*AB_t)[8][132];
    AB_t As2 = (AB_t)smraw;                      // [2][8][132] uint2, 16.9 KB
    AB_t Bs2 = (AB_t)(smraw + 16896);            // [2][8][132] uint2, 16.9 KB
    typedef float (*C_t)[65];
    C_t Cs = (C_t)smraw;                         // [128][65] float, 33.3 KB

    const int bz = blockIdx.z;
    const float* W = (bz == 0) ? Wq : (bz == 1 ? Wk : Wv);
    float* O = (bz == 0) ? g_q : (bz == 1 ? g_k : g_v);

    const int row0 = blockIdx.x * 128;
    const int col0 = blockIdx.y * 128;
    const int tid  = threadIdx.x;
    const int warp = tid >> 5;
    const int lane = tid & 31;
    const int wm   = (warp >> 2) * 64;   // 0 or 64
    const int wn   = (warp & 3) * 32;    // 0,32,64,96
    const int g    = lane >> 2;          // 0..7
    const int t    = lane & 3;           // 0..3

    const int ar = tid >> 1;            // 0..127
    const int ae = (tid & 1) * 8;       // 0 or 8
    const int pk = (tid & 1) * 4;       // 0 or 4
    const int pr = tid >> 5;            // 0..7
    const int n4 = (tid & 31) * 4;      // 0..124

    const float* xp = x + (size_t)(row0 + ar) * D_ + ae;
    const float* wp = W + (size_t)(2 * pr) * NKH_ + col0 + n4;

    float acc[4][4][4];
    #pragma unroll
    for (int i = 0; i < 4; i++)
        #pragma unroll
        for (int j = 0; j < 4; j++)
            #pragma unroll
            for (int r = 0; r < 4; r++) acc[i][j][r] = 0.f;

    float4 av0 = *(const float4*)(xp);
    float4 av1 = *(const float4*)(xp + 4);
    float4 wv0 = *(const float4*)(wp);
    float4 wv1 = *(const float4*)(wp + NKH_);
    As2[0][pk + 0][ar] = splitpair(av0.x, av0.y);
    As2[0][pk + 1][ar] = splitpair(av0.z, av0.w);
    As2[0][pk + 2][ar] = splitpair(av1.x, av1.y);
    As2[0][pk + 3][ar] = splitpair(av1.z, av1.w);
    Bs2[0][pr][n4 + 0] = splitpair(wv0.x, wv1.x);
    Bs2[0][pr][n4 + 1] = splitpair(wv0.y, wv1.y);
    Bs2[0][pr][n4 + 2] = splitpair(wv0.z, wv1.z);
    Bs2[0][pr][n4 + 3] = splitpair(wv0.w, wv1.w);
    __syncthreads();

    int cur = 0;
    #pragma unroll 1
    for (int k0 = 16; k0 <= D_; k0 += 16) {
        if (k0 < D_) {
            av0 = *(const float4*)(xp + k0);
            av1 = *(const float4*)(xp + k0 + 4);
            wv0 = *(const float4*)(wp + (size_t)k0 * NKH_);
            wv1 = *(const float4*)(wp + (size_t)k0 * NKH_ + NKH_);
        }

        unsigned ahi[4][4], alo[4][4], bhi[4][2], blo[4][2];
        #pragma unroll
        for (int i = 0; i < 4; i++) {
            const int m0 = wm + i * 16 + g;
            uint2 p0 = As2[cur][t][m0];
            uint2 p1 = As2[cur][t][m0 + 8];
            uint2 p2 = As2[cur][t + 4][m0];
            uint2 p3 = As2[cur][t + 4][m0 + 8];
            ahi[i][0] = p0.x; alo[i][0] = p0.y;
            ahi[i][1] = p1.x; alo[i][1] = p1.y;
            ahi[i][2] = p2.x; alo[i][2] = p2.y;
            ahi[i][3] = p3.x; alo[i][3] = p3.y;
        }
        #pragma unroll
        for (int j = 0; j < 4; j++) {
            const int n0 = wn + j * 8 + g;
            uint2 q0 = Bs2[cur][t][n0];
            uint2 q1 = Bs2[cur][t + 4][n0];
            bhi[j][0] = q0.x; blo[j][0] = q0.y;
            bhi[j][1] = q1.x; blo[j][1] = q1.y;
        }
        #pragma unroll
        for (int i = 0; i < 4; i++)
            #pragma unroll
            for (int j = 0; j < 4; j++) {
                mma_bf16(acc[i][j], ahi[i], bhi[j]);
                mma_bf16(acc[i][j], ahi[i], blo[j]);
                mma_bf16(acc[i][j], alo[i], bhi[j]);
            }

        if (k0 < D_) {
            const int nxt = cur ^ 1;
            As2[nxt][pk + 0][ar] = splitpair(av0.x, av0.y);
            As2[nxt][pk + 1][ar] = splitpair(av0.z, av0.w);
            As2[nxt][pk + 2][ar] = splitpair(av1.x, av1.y);
            As2[nxt][pk + 3][ar] = splitpair(av1.z, av1.w);
            Bs2[nxt][pr][n4 + 0] = splitpair(wv0.x, wv1.x);
            Bs2[nxt][pr][n4 + 1] = splitpair(wv0.y, wv1.y);
            Bs2[nxt][pr][n4 + 2] = splitpair(wv0.z, wv1.z);
            Bs2[nxt][pr][n4 + 3] = splitpair(wv0.w, wv1.w);
            __syncthreads();
            cur = nxt;
        }
    }

    // ---- Epilogue: stage 128x64 halves in smem, then coalesced float4 STG ----
    const int bb    = row0 >> 11;          // whole tile is one batch (row0 % 2048 + 128 <= 2048)
    const int sbase = row0 & (S_ - 1);
    #pragma unroll 1
    for (int hc = 0; hc < 2; hc++) {
        __syncthreads();   // mainloop (or previous half) done with smem
        // Write phase: this warp's acc entries with ncol in [hc*64, hc*64+64)
        #pragma unroll
        for (int j = 0; j < 4; j++) {
            if (((wn + j * 8) >> 6) == hc) {
                #pragma unroll
                for (int i = 0; i < 4; i++) {
                    #pragma unroll
                    for (int r = 0; r < 4; r++) {
                        const int mrow = wm + i * 16 + g + ((r >= 2) ? 8 : 0);
                        const int lcol = wn + j * 8 + 2 * t + (r & 1) - hc * 64;
                        Cs[mrow][lcol] = acc[i][j][r];
                    }
                }
            }
        }
        __syncthreads();
        // Read+store phase: 2048 segments of (h, s, 4 consecutive k)
        const int kb0 = (col0 + hc * 64) >> 4;
        #pragma unroll
        for (int u2 = 0; u2 < 8; u2++) {
            const int seg = tid + u2 * 256;   // 0..2047
            const int h   = seg >> 7;         // 0..15
            const int sl  = seg & 127;        // 0..127
            float4 v;
            v.x = Cs[sl][0 * 16 + h];
            v.y = Cs[sl][1 * 16 + h];
            v.z = Cs[sl][2 * 16 + h];
            v.w = Cs[sl][3 * 16 + h];
            *(float4*)&O[(((size_t)(bb * H_ + h)) * S_ + sbase + sl) * KS_ + kb0] = v;
        }
    }
}

// ---------------------------------------------------------------------------
// Kernel 2: causal flash attention + FUSED output projection. (R14 version)
// 64 queries / CTA, 128 threads. QK^T: 1x tf32. PV: 3-term bf16.
// Epilogue: T = (P V) @ W_h on bf16 mma, atomicAdd into d_out.
// ---------------------------------------------------------------------------
#define KSTR 68
#define VSTR 72
__global__ __launch_bounds__(128) void attn_mma(
    const float* __restrict__ kern,
    float* __restrict__ out)
{
    __shared__ union {
        struct { float Ks[64][KSTR]; unsigned VhP[32][VSTR]; unsigned VlP[32][VSTR]; } m;
        struct { unsigned WhH[32][VSTR]; unsigned WhL[32][VSTR]; } e;
    } sm;   // 35.8 KB

    const int bh = blockIdx.x;                       // 0..31
    const int qt = (S_ / 64 - 1) - blockIdx.y;       // heavy tiles first
    const int i0 = qt * 64;
    const int tid  = threadIdx.x;
    const int warp = tid >> 5;
    const int lane = tid & 31;
    const int g = lane >> 2;   // 0..7
    const int t = lane & 3;    // 0..3

    const float* qb = g_q + (size_t)bh * S_ * KS_;
    const float* kb = g_k + (size_t)bh * S_ * KS_;
    const float* vb = g_v + (size_t)bh * S_ * KS_;

    const int qr = i0 + warp * 16;
    unsigned qf[8][4];
    #pragma unroll
    for (int ka = 0; ka < 8; ka++) {
        qf[ka][0] = f2tf32(qb[(size_t)(qr + g)     * KS_ + ka * 8 + t]     * 0.125f);
        qf[ka][1] = f2tf32(qb[(size_t)(qr + g + 8) * KS_ + ka * 8 + t]     * 0.125f);
        qf[ka][2] = f2tf32(qb[(size_t)(qr + g)     * KS_ + ka * 8 + t + 4] * 0.125f);
        qf[ka][3] = f2tf32(qb[(size_t)(qr + g + 8) * KS_ + ka * 8 + t + 4] * 0.125f);
    }

    float acc[8][4];
    #pragma unroll
    for (int n = 0; n < 8; n++)
        #pragma unroll
        for (int r = 0; r < 4; r++) acc[n][r] = 0.f;
    float m0 = -1e30f, m1 = -1e30f, l0 = 0.f, l1 = 0.f;

    for (int j0 = 0; j0 <= i0; j0 += 64) {
        __syncthreads();
        const float4* kt = (const float4*)(kb + (size_t)j0 * KS_);
        const float4* vt = (const float4*)(vb + (size_t)j0 * KS_);
        // K: 1024 float4s, tf32-converted
        #pragma unroll
        for (int u = 0; u < 8; u++) {
            const int f = tid + u * 128;
            const int key = f >> 4;
            const int d4  = (f & 15) * 4;
            float4 kv = kt[f];
            *(float4*)&sm.m.Ks[key][d4] =
                make_float4(tf32f(kv.x), tf32f(kv.y), tf32f(kv.z), tf32f(kv.w));
        }
        // V: 512 key-pair tasks -> packed bf16 hi/lo planes
        #pragma unroll
        for (int u = 0; u < 4; u++) {
            const int f  = tid + u * 128;    // 0..511
            const int kp = f >> 4;           // 0..31
            const int d4 = (f & 15) * 4;
            float4 v0 = vt[(2 * kp) * 16 + (f & 15)];
            float4 v1 = vt[(2 * kp + 1) * 16 + (f & 15)];
            uint2 pa = splitpair(v0.x, v1.x);
            uint2 pb = splitpair(v0.y, v1.y);
            uint2 pc = splitpair(v0.z, v1.z);
            uint2 pd = splitpair(v0.w, v1.w);
            *(uint4*)&sm.m.VhP[kp][d4] = make_uint4(pa.x, pb.x, pc.x, pd.x);
            *(uint4*)&sm.m.VlP[kp][d4] = make_uint4(pa.y, pb.y, pc.y, pd.y);
        }
        __syncthreads();

        // ---- scores: S(16x64) = Q K^T ----
        float c[8][4];
        #pragma unroll
        for (int n = 0; n < 8; n++)
            #pragma unroll
            for (int r = 0; r < 4; r++) c[n][r] = 0.f;

        #pragma unroll
        for (int ka = 0; ka < 8; ka++) {
            #pragma unroll
            for (int n = 0; n < 8; n++) {
                unsigned b[2];
                b[0] = __float_as_uint(sm.m.Ks[n * 8 + g][ka * 8 + t]);
                b[1] = __float_as_uint(sm.m.Ks[n * 8 + g][ka * 8 + t + 4]);
                mma_tf32(c[n], qf[ka], b);
            }
        }

        // ---- causal mask (diagonal tile only) ----
        if (j0 == i0) {
            const int r0 = qr + g;
            const int r1 = r0 + 8;
            #pragma unroll
            for (int n = 0; n < 8; n++) {
                const int k0c = j0 + n * 8 + 2 * t;
                if (k0c     > r0) c[n][0] = -1e30f;
                if (k0c + 1 > r0) c[n][1] = -1e30f;
                if (k0c     > r1) c[n][2] = -1e30f;
                if (k0c + 1 > r1) c[n][3] = -1e30f;
            }
        }

        // ---- online softmax (rows g and g+8) ----
        float t0 = -1e30f, t1 = -1e30f;
        #pragma unroll
        for (int n = 0; n < 8; n++) {
            t0 = fmaxf(t0, fmaxf(c[n][0], c[n][1]));
            t1 = fmaxf(t1, fmaxf(c[n][2], c[n][3]));
        }
        t0 = fmaxf(t0, __shfl_xor_sync(0xffffffffu, t0, 1));
        t0 = fmaxf(t0, __shfl_xor_sync(0xffffffffu, t0, 2));
        t1 = fmaxf(t1, __shfl_xor_sync(0xffffffffu, t1, 1));
        t1 = fmaxf(t1, __shfl_xor_sync(0xffffffffu, t1, 2));
        const float nm0 = fmaxf(m0, t0);
        const float nm1 = fmaxf(m1, t1);
        const float f0 = __expf(m0 - nm0);
        const float f1 = __expf(m1 - nm1);
        m0 = nm0; m1 = nm1;
        l0 *= f0;  l1 *= f1;
        #pragma unroll
        for (int n = 0; n < 8; n++) {
            acc[n][0] *= f0; acc[n][1] *= f0;
            acc[n][2] *= f1; acc[n][3] *= f1;
        }
        float ps0 = 0.f, ps1 = 0.f;
        #pragma unroll
        for (int n = 0; n < 8; n++) {
            c[n][0] = __expf(c[n][0] - m0);
            c[n][1] = __expf(c[n][1] - m0);
            c[n][2] = __expf(c[n][2] - m1);
            c[n][3] = __expf(c[n][3] - m1);
            ps0 += c[n][0] + c[n][1];
            ps1 += c[n][2] + c[n][3];
        }
        ps0 += __shfl_xor_sync(0xffffffffu, ps0, 1);
        ps0 += __shfl_xor_sync(0xffffffffu, ps0, 2);
        ps1 += __shfl_xor_sync(0xffffffffu, ps1, 1);
        ps1 += __shfl_xor_sync(0xffffffffu, ps1, 2);
        l0 += ps0; l1 += ps1;

        // ---- PV: acc += P V (bf16 3-term, interleaved order) ----
        #pragma unroll
        for (int ka = 0; ka < 4; ka++) {
            unsigned ahi[4], alo[4];
            uint2 p;
            p = splitpair(c[2*ka][0],     c[2*ka][1]);     ahi[0] = p.x; alo[0] = p.y;
            p = splitpair(c[2*ka][2],     c[2*ka][3]);     ahi[1] = p.x; alo[1] = p.y;
            p = splitpair(c[2*ka+1][0],   c[2*ka+1][1]);   ahi[2] = p.x; alo[2] = p.y;
            p = splitpair(c[2*ka+1][2],   c[2*ka+1][3]);   ahi[3] = p.x; alo[3] = p.y;
            #pragma unroll
            for (int n = 0; n < 8; n++) {
                unsigned bh2[2], bl2[2];
                bh2[0] = sm.m.VhP[ka * 8 + t][n * 8 + g];
                bh2[1] = sm.m.VhP[ka * 8 + t + 4][n * 8 + g];
                bl2[0] = sm.m.VlP[ka * 8 + t][n * 8 + g];
                bl2[1] = sm.m.VlP[ka * 8 + t + 4][n * 8 + g];
                mma_bf16(acc[n], ahi, bh2);
                mma_bf16(acc[n], ahi, bl2);
                mma_bf16(acc[n], alo, bh2);
            }
        }
    }

    // ================= FUSED OUTPUT PROJECTION =================
    const float inv0 = 1.f / l0;
    const float inv1 = 1.f / l1;
    const int bb = bh >> 4;        // / H_
    const int h  = bh & (H_ - 1);

    __syncthreads();
    #pragma unroll
    for (int u = 0; u < 16; u++) {
        const int f  = tid + u * 128;    // 0..2047
        const int kp = f >> 6;           // 0..31
        const int j  = f & 63;
        const float e0 = kern[((size_t)(2 * kp)     * H_ + h) * KS_ + j];
        const float e1 = kern[((size_t)(2 * kp + 1) * H_ + h) * KS_ + j];
        uint2 p = splitpair(e0, e1);
        sm.e.WhH[kp][j] = p.x;
        sm.e.WhL[kp][j] = p.y;
    }
    __syncthreads();

    // T(16x64) = normalized(P V) @ W_h  — same fragment mapping as PV
    float o[8][4];
    #pragma unroll
    for (int n = 0; n < 8; n++)
        #pragma unroll
        for (int r = 0; r < 4; r++) o[n][r] = 0.f;

    #pragma unroll
    for (int ka = 0; ka < 4; ka++) {
        unsigned ahi[4], alo[4];
        uint2 p;
        p = splitpair(acc[2*ka][0]   * inv0, acc[2*ka][1]   * inv0); ahi[0] = p.x; alo[0] = p.y;
        p = splitpair(acc[2*ka][2]   * inv1, acc[2*ka][3]   * inv1); ahi[1] = p.x; alo[1] = p.y;
        p = splitpair(acc[2*ka+1][0] * inv0, acc[2*ka+1][1] * inv0); ahi[2] = p.x; alo[2] = p.y;
        p = splitpair(acc[2*ka+1][2] * inv1, acc[2*ka+1][3] * inv1); ahi[3] = p.x; alo[3] = p.y;
        #pragma unroll
        for (int n = 0; n < 8; n++) {
            unsigned bh2[2], bl2[2];
            bh2[0] = sm.e.WhH[ka * 8 + t][n * 8 + g];
            bh2[1] = sm.e.WhH[ka * 8 + t + 4][n * 8 + g];
            bl2[0] = sm.e.WhL[ka * 8 + t][n * 8 + g];
            bl2[1] = sm.e.WhL[ka * 8 + t + 4][n * 8 + g];
            mma_bf16(o[n], ahi, bh2);
            mma_bf16(o[n], ahi, bl2);
            mma_bf16(o[n], alo, bh2);
        }
    }

    // Accumulate into d_out (rows bb*S + qr+g / +8, cols n*8+2t..+1)
    float* or0 = out + (size_t)(bb * S_ + qr + g) * KS_;
    float* or1 = out + (size_t)(bb * S_ + qr + g + 8) * KS_;
    #pragma unroll
    for (int n = 0; n < 8; n++) {
        const int jc = n * 8 + 2 * t;
        atomicAdd(&or0[jc],     o[n][0]);
        atomicAdd(&or0[jc + 1], o[n][1]);
        atomicAdd(&or1[jc],     o[n][2]);
        atomicAdd(&or1[jc + 1], o[n][3]);
    }
}

// ---------------------------------------------------------------------------
// Kernel 3: zero d_out (poisoned by harness; attn accumulates into it).
// ---------------------------------------------------------------------------
__global__ __launch_bounds__(256) void zero_out(float4* __restrict__ out)
{
    out[blockIdx.x * 256 + threadIdx.x] = make_float4(0.f, 0.f, 0.f, 0.f);
}

// ---------------------------------------------------------------------------
extern "C" void kernel_launch(void* const* d_in, const int* in_sizes, int n_in,
                              void* d_out, int out_size)
{
    (void)in_sizes; (void)n_in; (void)out_size;
    const float* x  = (const float*)d_in[0];
    const float* Wq = (const float*)d_in[1];
    const float* Wk = (const float*)d_in[2];
    const float* Wv = (const float*)d_in[3];
    const float* kr = (const float*)d_in[4];
    float* out = (float*)d_out;

    zero_out<<<(B_ * S_ * KS_) / 1024, 256>>>((float4*)out);

    dim3 g1(B_ * S_ / 128, NKH_ / 128, 3);   // (32, 8, 3)
    qkv_gemm<<<g1, 256>>>(x, Wq, Wk, Wv);

    dim3 g2(NBH_, S_ / 64);                  // (32, 32)
    attn_mma<<<g2, 128>>>(kr, out);
}